// round 12
// baseline (speedup 1.0000x reference)
#include <cuda_runtime.h>

// ---------------------------------------------------------------------------
// RPN pipeline, all fp32 (ordering-sensitive: top-k + greedy NMS).
//   conv3x3+relu -> heads(1x1) -> decode+sigmoid+hist -> radix-select top6000
//   -> rank-scatter -> clip/valid -> NMS bitmask (triangular) -> warp scan
//   -> top-300
// memset split in 3 so conv is the 4th launch (ncu capture slot).
// ---------------------------------------------------------------------------

#define NPROP 36864
#define NPRE  6000
#define NPOST 300
#define NW    94        // 6000 bits -> 94 x 64-bit words
#define NSEL  8192      // candidate capacity (top bin adds ~400 over 6000)
#define NBIN  524288    // histogram bins: kd>>12, kd < 2^31
#define NMASKW (NPRE * NW)   // 564000 mask words

__device__ float g_y[512 * 4096];          // conv1 output (relu'd)
__device__ float g_cls[9 * 4096];
__device__ float g_box[36 * 4096];
__device__ float g_preds[NPROP * 4];       // decoded boxes (unclipped)
__device__ float g_sig[NPROP];             // sigmoid scores
__device__ unsigned int g_kd[NPROP];       // descending-monotone score key
__device__ int g_hist[NBIN];
__device__ int g_coarse[1024];
__device__ int g_cut;                      // cutoff bin
__device__ int g_cnt;                      // gather counter
__device__ unsigned long long g_sel[NSEL]; // gathered candidate keys
__device__ unsigned long long g_top[NPRE]; // exact sorted top-6000 keys
__device__ float g_b6k[NPRE * 4];          // clipped boxes of top-6000
__device__ float g_v6k[NPRE];              // sigmoid values of top-6000
__device__ unsigned int g_valid32[192];    // validity bits (ballot words)
__device__ unsigned long long g_mask[NMASKW];
__device__ unsigned long long g_keepbits[NW];

// ---------------------------------------------------------------------------
// memset slices (3 kernels so conv is the 4th launch -> gets profiled).
// ---------------------------------------------------------------------------
__global__ void __launch_bounds__(256) memset_a()
{
    const int idx = blockIdx.x * 256 + threadIdx.x;   // 256 blocks -> 65536
    const int hb = idx * 4;
#pragma unroll
    for (int q = 0; q < 4; ++q) g_hist[hb + q] = 0;    // [0, 262144)
#pragma unroll
    for (int q = 0; q < 5; ++q) {
        int m = idx * 5 + q;                           // [0, 327680) guard
        if (m < NMASKW / 2) g_mask[m] = 0ull;
    }
}

__global__ void __launch_bounds__(256) memset_b()
{
    const int idx = blockIdx.x * 256 + threadIdx.x;
    const int hb = 262144 + idx * 4;
#pragma unroll
    for (int q = 0; q < 4; ++q) g_hist[hb + q] = 0;    // [262144, 524288)
#pragma unroll
    for (int q = 0; q < 5; ++q) {
        int m = NMASKW / 2 + idx * 5 + q;
        if (m < NMASKW) g_mask[m] = 0ull;
    }
}

__global__ void __launch_bounds__(256) memset_c()
{
    const int t = threadIdx.x;                         // 1 block, 256 thr
    if (t == 0) g_cnt = 0;
    if (t < 192) g_valid32[t] = 0u;
#pragma unroll
    for (int q = 0; q < 32; ++q) {
        int i = t * 32 + q;                            // covers NSEL = 8192
        g_sel[i] = 0xFFFFFFFF00000000ull | (unsigned int)i;
    }
}

// ---------------------------------------------------------------------------
// Conv 3x3 (512->512, 64x64, pad 1) + bias + ReLU.
// Block: 64 oc x 32 px (half row). BK=8 ic. 128 thr, 8(oc) x 2(px) tiles.
// 1024 blocks = 148 SMs x 6.92 -> wave imbalance 16% -> 1.2%, occupancy 2x.
// Loop nest (ic0->icl->kh->kw) and per-output FFMA chain identical to the
// validated kernel -> conv output bit-exact.
// ---------------------------------------------------------------------------
__global__ void __launch_bounds__(128) conv3x3_relu(
    const float* __restrict__ x,      // (512,64,64)
    const float* __restrict__ w,      // (512,512,3,3)
    const float* __restrict__ bias)   // (512)
{
    __shared__ float Xs[8 * 3 * 34];                 // [icl][row][col -1..32]
    __shared__ __align__(16) float Ws[72 * 68];      // [icl*9+tap][oc]

    const int bx      = blockIdx.x;        // 0..127
    const int yrow    = bx >> 1;           // 0..63
    const int colbase = (bx & 1) * 32;     // 0 or 32
    const int oc0     = blockIdx.y * 64;   // 8 tiles
    const int tid     = threadIdx.x;       // 0..127
    const int tx      = tid & 15;          // 16 px groups of 2
    const int ty      = tid >> 4;          // 8 oc groups of 8
    const int px0     = tx * 2;            // local col 0..30
    const int oc_t    = ty * 8;

    float acc[8][2];
#pragma unroll
    for (int i = 0; i < 8; ++i) { acc[i][0] = 0.f; acc[i][1] = 0.f; }

    for (int ic0 = 0; ic0 < 512; ic0 += 8) {
        // stage X halo: 8 ic x 3 rows x 34 cols (global cols colbase-1..+32)
        for (int idx = tid; idx < 8 * 3 * 34; idx += 128) {
            int icl = idx / 102;
            int rem = idx - icl * 102;
            int r   = rem / 34;
            int c   = rem - r * 34 - 1 + colbase;   // global col
            int gy  = yrow - 1 + r;
            float v = 0.f;
            if ((unsigned)gy < 64u && (unsigned)c < 64u)
                v = x[(ic0 + icl) * 4096 + gy * 64 + c];
            Xs[idx] = v;
        }
        // stage W: 64 oc x 72 (coalesced 72-runs per oc)
        for (int idx = tid; idx < 64 * 72; idx += 128) {
            int oc = idx / 72;
            int r  = idx - oc * 72;            // icl*9 + tap
            Ws[r * 68 + oc] = w[(oc0 + oc) * 4608 + ic0 * 9 + r];
        }
        __syncthreads();

#pragma unroll 4
        for (int icl = 0; icl < 8; ++icl) {
#pragma unroll
            for (int kh = 0; kh < 3; ++kh) {
                float xv[4];
                const int xb = icl * 102 + kh * 34 + px0;
#pragma unroll
                for (int t = 0; t < 4; ++t) xv[t] = Xs[xb + t];
#pragma unroll
                for (int kw = 0; kw < 3; ++kw) {
                    const int wb = (icl * 9 + kh * 3 + kw) * 68 + oc_t;
                    const float4 wva = *reinterpret_cast<const float4*>(&Ws[wb]);
                    const float4 wvb = *reinterpret_cast<const float4*>(&Ws[wb + 4]);
                    const float w0 = wva.x, w1 = wva.y, w2 = wva.z, w3 = wva.w;
                    const float w4 = wvb.x, w5 = wvb.y, w6 = wvb.z, w7 = wvb.w;
#pragma unroll
                    for (int jx = 0; jx < 2; ++jx) {
                        float xvv = xv[kw + jx];
                        acc[0][jx] += w0 * xvv;
                        acc[1][jx] += w1 * xvv;
                        acc[2][jx] += w2 * xvv;
                        acc[3][jx] += w3 * xvv;
                        acc[4][jx] += w4 * xvv;
                        acc[5][jx] += w5 * xvv;
                        acc[6][jx] += w6 * xvv;
                        acc[7][jx] += w7 * xvv;
                    }
                }
            }
        }
        __syncthreads();
    }

#pragma unroll
    for (int i = 0; i < 8; ++i) {
        float b = bias[oc0 + oc_t + i];
#pragma unroll
        for (int jx = 0; jx < 2; ++jx) {
            float v = acc[i][jx] + b;
            g_y[(oc0 + oc_t + i) * 4096 + yrow * 64 + colbase + px0 + jx] =
                fmaxf(v, 0.f);
        }
    }
}

// ---------------------------------------------------------------------------
// 1x1 heads: cls (9) + box (36). One thread per pixel, 45 accumulators.
// 128 blocks x 32 px -> 128 SMs covered (was 32). Per-pixel math unchanged.
// ---------------------------------------------------------------------------
__global__ void __launch_bounds__(32) heads_kernel(
    const float* __restrict__ cw, const float* __restrict__ cb,
    const float* __restrict__ bw, const float* __restrict__ bb)
{
    __shared__ float ws[45 * 32];
    const int p = blockIdx.x * 32 + threadIdx.x;
    float acc[45];
#pragma unroll
    for (int c = 0; c < 45; ++c) acc[c] = 0.f;

    for (int ic0 = 0; ic0 < 512; ic0 += 32) {
        for (int idx = threadIdx.x; idx < 45 * 32; idx += 32) {
            int c = idx >> 5, icl = idx & 31;
            ws[idx] = (c < 9) ? cw[c * 512 + ic0 + icl]
                              : bw[(c - 9) * 512 + ic0 + icl];
        }
        __syncthreads();
        for (int icl = 0; icl < 32; ++icl) {
            float v = g_y[(ic0 + icl) * 4096 + p];
#pragma unroll
            for (int c = 0; c < 45; ++c) acc[c] += ws[c * 32 + icl] * v;
        }
        __syncthreads();
    }
#pragma unroll
    for (int a = 0; a < 9; ++a)  g_cls[a * 4096 + p] = acc[a] + cb[a];
#pragma unroll
    for (int c = 0; c < 36; ++c) g_box[c * 4096 + p] = acc[9 + c] + bb[c];
}

// ---------------------------------------------------------------------------
// Decode boxes (exact reshape(-1,4) aliasing), sigmoid, key + histogram.
// ---------------------------------------------------------------------------
__global__ void decode_kernel(const float* __restrict__ anchors)
{
    const int g = blockIdx.x * 256 + threadIdx.x;      // 144*256 == NPROP
    const int c  = g >> 10;
    const int p0 = (g & 1023) << 2;
    float dx = g_box[c * 4096 + p0 + 0];
    float dy = g_box[c * 4096 + p0 + 1];
    float dw = g_box[c * 4096 + p0 + 2];
    float dh = g_box[c * 4096 + p0 + 3];
    float ax1 = anchors[g * 4 + 0], ay1 = anchors[g * 4 + 1];
    float ax2 = anchors[g * 4 + 2], ay2 = anchors[g * 4 + 3];
    float aw = ax2 - ax1, ah = ay2 - ay1;
    float ax = ax1 + 0.5f * aw, ay = ay1 + 0.5f * ah;
    const float BBOX_CLIP = 4.135166556742356f;   // log(1000/16)
    dw = fminf(dw, BBOX_CLIP);
    dh = fminf(dh, BBOX_CLIP);
    float px = dx * aw + ax, py = dy * ah + ay;
    float pw = expf(dw) * aw, ph = expf(dh) * ah;
    g_preds[g * 4 + 0] = px - 0.5f * pw;
    g_preds[g * 4 + 1] = py - 0.5f * ph;
    g_preds[g * 4 + 2] = px + 0.5f * pw;
    g_preds[g * 4 + 3] = py + 0.5f * ph;

    float s = 1.f / (1.f + expf(-g_cls[g]));
    g_sig[g] = s;
    unsigned int u = __float_as_uint(s);
    u ^= (u & 0x80000000u) ? 0xFFFFFFFFu : 0x80000000u;   // ascending-monotone
    unsigned int kd = ~u;                                  // descending
    g_kd[g] = kd;
    atomicAdd(&g_hist[kd >> 12], 1);
}

// ---------------------------------------------------------------------------
// Coarse histogram sums: 1024 chunks of 512 bins.
// ---------------------------------------------------------------------------
__global__ void __launch_bounds__(256) hist_coarse()
{
    __shared__ int sred[256];
    const int b = blockIdx.x, t = threadIdx.x;
    int v = g_hist[b * 512 + t] + g_hist[b * 512 + 256 + t];
    sred[t] = v;
    __syncthreads();
    for (int d = 128; d > 0; d >>= 1) {
        if (t < d) sred[t] += sred[t + d];
        __syncthreads();
    }
    if (t == 0) g_coarse[b] = sred[0];
}

// ---------------------------------------------------------------------------
// Find cutoff bin: first bin B with cumulative(kd ascending) >= NPRE.
// ---------------------------------------------------------------------------
__global__ void __launch_bounds__(1024) findbin_kernel()
{
    __shared__ int s[1024];
    __shared__ int selblk, selbase;
    const int t = threadIdx.x;

    s[t] = g_coarse[t];
    __syncthreads();
    for (int d = 1; d < 1024; d <<= 1) {
        int v = s[t];
        int add = (t >= d) ? s[t - d] : 0;
        __syncthreads();
        s[t] = v + add;
        __syncthreads();
    }
    {
        int cum = s[t];
        int prev = (t == 0) ? 0 : s[t - 1];
        if (cum >= NPRE && prev < NPRE) { selblk = t; selbase = prev; }
    }
    __syncthreads();
    const int bb = selblk, base = selbase;

    __syncthreads();
    s[t] = (t < 512) ? g_hist[bb * 512 + t] : 0;
    __syncthreads();
    for (int d = 1; d < 1024; d <<= 1) {
        int v = s[t];
        int add = (t >= d) ? s[t - d] : 0;
        __syncthreads();
        s[t] = v + add;
        __syncthreads();
    }
    if (t < 512) {
        int cum = base + s[t];
        int prev = base + ((t == 0) ? 0 : s[t - 1]);
        if (cum >= NPRE && prev < NPRE) g_cut = bb * 512 + t;
    }
}

// ---------------------------------------------------------------------------
// Gather all items in bins <= cut (superset of exact top-6000).
// ---------------------------------------------------------------------------
__global__ void gather_kernel()
{
    const int g = blockIdx.x * 256 + threadIdx.x;      // == NPROP threads
    const unsigned int kd = g_kd[g];
    if ((int)(kd >> 12) <= g_cut) {
        int pos = atomicAdd(&g_cnt, 1);
        if (pos < NSEL)
            g_sel[pos] = ((unsigned long long)kd << 32) | (unsigned int)g;
    }
}

// ---------------------------------------------------------------------------
// Rank-by-counting over the <=8192 candidates; scatter ranks < 6000.
// ---------------------------------------------------------------------------
__global__ void __launch_bounds__(256) rank_scatter()
{
    __shared__ unsigned long long sk[2048];
    const int t = blockIdx.x * 256 + threadIdx.x;      // 32 blocks -> 8192
    const unsigned long long my = g_sel[t];
    int r = 0;
    for (int c0 = 0; c0 < NSEL; c0 += 2048) {
        for (int j = threadIdx.x; j < 2048; j += 256) sk[j] = g_sel[c0 + j];
        __syncthreads();
#pragma unroll 8
        for (int j = 0; j < 2048; ++j) r += (sk[j] < my) ? 1 : 0;
        __syncthreads();
    }
    if (r < NPRE) g_top[r] = my;
}

// ---------------------------------------------------------------------------
// Gather top-6000: clip to image, validity bits (ballot), score.
// ---------------------------------------------------------------------------
__global__ void __launch_bounds__(256) post_topk(const int* __restrict__ img)
{
    const int t = blockIdx.x * 256 + threadIdx.x;      // 24 blocks -> 6144
    bool valid = false;
    if (t < NPRE) {
        const unsigned long long key = g_top[t];
        const int g = (int)(key & 0xFFFFFFFFull);
        const float himg = (float)img[0], wimg = (float)img[1];
        float x1 = fminf(fmaxf(g_preds[g * 4 + 0], 0.f), wimg);
        float y1 = fminf(fmaxf(g_preds[g * 4 + 1], 0.f), himg);
        float x2 = fminf(fmaxf(g_preds[g * 4 + 2], 0.f), wimg);
        float y2 = fminf(fmaxf(g_preds[g * 4 + 3], 0.f), himg);
        g_b6k[t * 4 + 0] = x1;
        g_b6k[t * 4 + 1] = y1;
        g_b6k[t * 4 + 2] = x2;
        g_b6k[t * 4 + 3] = y2;
        g_v6k[t] = g_sig[g];
        valid = ((x2 - x1) >= 16.f) && ((y2 - y1) >= 16.f);
    }
    unsigned int bal = __ballot_sync(0xFFFFFFFFu, valid);
    if ((threadIdx.x & 31) == 0) g_valid32[t >> 5] = bal;
}

// ---------------------------------------------------------------------------
// NMS suppression bitmask, TRIANGULAR (g_mask pre-zeroed).
// mask[i][cb] bit jj set iff j>i and IoU(i,j)>0.7.
// ---------------------------------------------------------------------------
__global__ void __launch_bounds__(64) nms_mask()
{
    __shared__ float cbox[64 * 4];
    const int cb = blockIdx.x, rb = blockIdx.y;
    if (cb < rb) return;                   // lower triangle: all-zero words
    const int cbase = cb * 64;
    const int ccount = min(64, NPRE - cbase);
    if ((int)threadIdx.x < ccount) {
#pragma unroll
        for (int q = 0; q < 4; ++q)
            cbox[threadIdx.x * 4 + q] = g_b6k[(cbase + threadIdx.x) * 4 + q];
    }
    __syncthreads();
    const int i = rb * 64 + threadIdx.x;
    if (i >= NPRE) return;
    const float x1 = g_b6k[i * 4 + 0], y1 = g_b6k[i * 4 + 1];
    const float x2 = g_b6k[i * 4 + 2], y2 = g_b6k[i * 4 + 3];
    const float area_i = (x2 - x1) * (y2 - y1);
    unsigned long long bits = 0ull;
    for (int jj = 0; jj < ccount; ++jj) {
        int j = cbase + jj;
        if (j <= i) continue;
        float bx1 = cbox[jj * 4 + 0], by1 = cbox[jj * 4 + 1];
        float bx2 = cbox[jj * 4 + 2], by2 = cbox[jj * 4 + 3];
        float ix1 = fmaxf(x1, bx1), iy1 = fmaxf(y1, by1);
        float ix2 = fminf(x2, bx2), iy2 = fminf(y2, by2);
        float iw = fmaxf(ix2 - ix1, 0.f), ih = fmaxf(iy2 - iy1, 0.f);
        float inter = iw * ih;
        float uni = area_i + (bx2 - bx1) * (by2 - by1) - inter;
        float iou = (uni > 0.f) ? (inter / uni) : 0.f;
        if (iou > 0.7f) bits |= (1ull << jj);
    }
    g_mask[i * NW + cb] = bits;
}

// ---------------------------------------------------------------------------
// Greedy scan: single warp, removed-bits in registers, 8-deep prefetch,
// BATCHED aliveness: all 8 rows of a batch share one rem word, so the
// intra-batch greedy chain is resolved locally (every lane computes on its
// own registers; one shfl broadcasts the owner lane's 8-bit alive mask).
// Exactly equivalent to the row-serial greedy (masks only have j>i bits).
// ---------------------------------------------------------------------------
__device__ __forceinline__ void scan_load8(
    unsigned long long (&buf)[8][3], int rowbase, int lane)
{
#pragma unroll
    for (int r = 0; r < 8; ++r) {
        const int i = rowbase + r;
        const bool ok = (i < NPRE);
        const unsigned long long* p = g_mask + (size_t)i * NW;
        buf[r][0] = ok ? p[lane] : 0ull;
        buf[r][1] = ok ? p[lane + 32] : 0ull;
        buf[r][2] = (ok && lane < 30) ? p[lane + 64] : 0ull;
    }
}

__device__ __forceinline__ void scan_proc8(
    const unsigned long long (&buf)[8][3], int base, int lane,
    unsigned long long (&rem)[3], unsigned long long (&keepw)[3])
{
    const int w    = base >> 6;            // same word for all 8 rows (8|64)
    const int src  = w & 31;
    const int slot = w >> 5;
    const int b0   = base & 63;

    // Speculative local greedy on every lane (only lane src's result used).
    unsigned long long localw = (slot == 0) ? rem[0]
                              : (slot == 1) ? rem[1] : rem[2];
    unsigned int am = 0;
#pragma unroll
    for (int r = 0; r < 8; ++r) {
        if (((localw >> (b0 + r)) & 1ull) == 0ull) {
            am |= (1u << r);
            localw |= (slot == 0) ? buf[r][0]
                    : (slot == 1) ? buf[r][1] : buf[r][2];
        }
    }
    am = __shfl_sync(0xFFFFFFFFu, am, src);

#pragma unroll
    for (int r = 0; r < 8; ++r) {
        if ((am >> r) & 1u) {
            rem[0] |= buf[r][0];
            rem[1] |= buf[r][1];
            rem[2] |= buf[r][2];
        }
    }
    if (lane == src) {
        if (slot == 0)      keepw[0] |= (unsigned long long)am << b0;
        else if (slot == 1) keepw[1] |= (unsigned long long)am << b0;
        else                keepw[2] |= (unsigned long long)am << b0;
    }
}

__global__ void __launch_bounds__(32) nms_scan_warp()
{
    const int lane = threadIdx.x;
    unsigned long long rem[3], keepw[3] = {0ull, 0ull, 0ull};
#pragma unroll
    for (int s = 0; s < 3; ++s) {
        const int w = lane + 32 * s;
        if (w < NW) {
            unsigned long long lo = g_valid32[2 * w];
            unsigned long long hi = g_valid32[2 * w + 1];
            rem[s] = ~((hi << 32) | lo);
        } else {
            rem[s] = ~0ull;
        }
    }
    unsigned long long A[8][3], B[8][3];
    scan_load8(A, 0, lane);
    for (int base = 0; base < NPRE; base += 16) {
        scan_load8(B, base + 8, lane);
        scan_proc8(A, base, lane, rem, keepw);
        scan_load8(A, base + 16, lane);
        scan_proc8(B, base + 8, lane, rem, keepw);
    }
#pragma unroll
    for (int s = 0; s < 3; ++s) {
        const int w = lane + 32 * s;
        if (w < NW) g_keepbits[w] = keepw[s];
    }
}

// ---------------------------------------------------------------------------
// Finalize: kept entries in order, then suppressed by ascending index with
// score -1; first 300 -> out (boxes [300,4] then scores [300]).
// ---------------------------------------------------------------------------
__global__ void __launch_bounds__(256) finalize(float* __restrict__ out)
{
    __shared__ int ckeep[256], csupp[256];
    __shared__ int okeep[256], osupp[256];
    __shared__ int totk;
    const int t = threadIdx.x;
    const int beg = t * 24;
    const int end = min(beg + 24, NPRE);
    int ck = 0;
    for (int i = beg; i < end; ++i)
        ck += (int)((g_keepbits[i >> 6] >> (i & 63)) & 1ull);
    ckeep[t] = ck;
    csupp[t] = (end > beg ? (end - beg) : 0) - ck;
    __syncthreads();
    if (t == 0) {
        int a = 0, b = 0;
        for (int q = 0; q < 256; ++q) {
            okeep[q] = a; osupp[q] = b;
            a += ckeep[q]; b += csupp[q];
        }
        totk = a;
    }
    __syncthreads();
    int rk = okeep[t];
    int rs = totk + osupp[t];
    for (int i = beg; i < end; ++i) {
        bool kp = ((g_keepbits[i >> 6] >> (i & 63)) & 1ull) != 0ull;
        int rank = kp ? (rk++) : (rs++);
        if (rank < NPOST) {
            out[rank * 4 + 0] = g_b6k[i * 4 + 0];
            out[rank * 4 + 1] = g_b6k[i * 4 + 1];
            out[rank * 4 + 2] = g_b6k[i * 4 + 2];
            out[rank * 4 + 3] = g_b6k[i * 4 + 3];
            out[NPOST * 4 + rank] = kp ? g_v6k[i] : -1.0f;
        }
    }
}

// ---------------------------------------------------------------------------
extern "C" void kernel_launch(void* const* d_in, const int* in_sizes, int n_in,
                              void* d_out, int out_size)
{
    const float* feature = (const float*)d_in[0];   // (1,512,64,64)
    const float* anchors = (const float*)d_in[1];   // (36864,4)
    const int*   imgsh   = (const int*)d_in[2];     // (2,)
    const float* c1w     = (const float*)d_in[3];   // (512,512,3,3)
    const float* c1b     = (const float*)d_in[4];   // (512,)
    const float* clsw    = (const float*)d_in[5];   // (9,512,1,1)
    const float* clsb    = (const float*)d_in[6];   // (9,)
    const float* boxw    = (const float*)d_in[7];   // (36,512,1,1)
    const float* boxb    = (const float*)d_in[8];   // (36,)
    float* out = (float*)d_out;                     // 1500 floats

    memset_a<<<256, 256>>>();                       // launch 1
    memset_b<<<256, 256>>>();                       // launch 2
    memset_c<<<1, 256>>>();                         // launch 3
    conv3x3_relu<<<dim3(128, 8), 128>>>(feature, c1w, c1b);  // launch 4 (profiled)
    heads_kernel<<<128, 32>>>(clsw, clsb, boxw, boxb);
    decode_kernel<<<NPROP / 256, 256>>>(anchors);
    hist_coarse<<<1024, 256>>>();
    findbin_kernel<<<1, 1024>>>();
    gather_kernel<<<NPROP / 256, 256>>>();
    rank_scatter<<<NSEL / 256, 256>>>();
    post_topk<<<24, 256>>>(imgsh);
    nms_mask<<<dim3(NW, NW), 64>>>();
    nms_scan_warp<<<1, 32>>>();
    finalize<<<1, 256>>>(out);
}

// round 14
// speedup vs baseline: 1.7297x; 1.7297x over previous
#include <cuda_runtime.h>

// ---------------------------------------------------------------------------
// RPN pipeline, all fp32 (ordering-sensitive: top-k + greedy NMS).
//   conv3x3+relu -> heads(1x1) -> decode+sigmoid+hist -> radix-select top6000
//   -> rank-scatter -> clip/valid -> NMS bitmask (triangular) -> warp scan
//   -> top-300
// Conv/heads: validated R11 shapes. Single experiment: batched NMS scan.
// ---------------------------------------------------------------------------

#define NPROP 36864
#define NPRE  6000
#define NPOST 300
#define NW    94        // 6000 bits -> 94 x 64-bit words
#define NSEL  8192      // candidate capacity (top bin adds ~400 over 6000)
#define NBIN  524288    // histogram bins: kd>>12, kd < 2^31
#define NMASKW (NPRE * NW)   // 564000 mask words

__device__ float g_y[512 * 4096];          // conv1 output (relu'd)
__device__ float g_cls[9 * 4096];
__device__ float g_box[36 * 4096];
__device__ float g_preds[NPROP * 4];       // decoded boxes (unclipped)
__device__ float g_sig[NPROP];             // sigmoid scores
__device__ unsigned int g_kd[NPROP];       // descending-monotone score key
__device__ int g_hist[NBIN];
__device__ int g_coarse[1024];
__device__ int g_cut;                      // cutoff bin
__device__ int g_cnt;                      // gather counter
__device__ unsigned long long g_sel[NSEL]; // gathered candidate keys
__device__ unsigned long long g_top[NPRE]; // exact sorted top-6000 keys
__device__ float g_b6k[NPRE * 4];          // clipped boxes of top-6000
__device__ float g_v6k[NPRE];              // sigmoid values of top-6000
__device__ unsigned int g_valid32[192];    // validity bits (ballot words)
__device__ unsigned long long g_mask[NMASKW];
__device__ unsigned long long g_keepbits[NW];

// ---------------------------------------------------------------------------
// memset slices (3 kernels so conv is the 4th launch -> gets profiled).
// ---------------------------------------------------------------------------
__global__ void __launch_bounds__(256) memset_a()
{
    const int idx = blockIdx.x * 256 + threadIdx.x;   // 256 blocks -> 65536
    const int hb = idx * 4;
#pragma unroll
    for (int q = 0; q < 4; ++q) g_hist[hb + q] = 0;    // [0, 262144)
#pragma unroll
    for (int q = 0; q < 5; ++q) {
        int m = idx * 5 + q;                           // [0, 327680) guard
        if (m < NMASKW / 2) g_mask[m] = 0ull;
    }
}

__global__ void __launch_bounds__(256) memset_b()
{
    const int idx = blockIdx.x * 256 + threadIdx.x;
    const int hb = 262144 + idx * 4;
#pragma unroll
    for (int q = 0; q < 4; ++q) g_hist[hb + q] = 0;    // [262144, 524288)
#pragma unroll
    for (int q = 0; q < 5; ++q) {
        int m = NMASKW / 2 + idx * 5 + q;
        if (m < NMASKW) g_mask[m] = 0ull;
    }
}

__global__ void __launch_bounds__(256) memset_c()
{
    const int t = threadIdx.x;                         // 1 block, 256 thr
    if (t == 0) g_cnt = 0;
    if (t < 192) g_valid32[t] = 0u;
#pragma unroll
    for (int q = 0; q < 32; ++q) {
        int i = t * 32 + q;                            // covers NSEL = 8192
        g_sel[i] = 0xFFFFFFFF00000000ull | (unsigned int)i;
    }
}

// ---------------------------------------------------------------------------
// Conv 3x3 (512->512, 64x64, pad 1) + bias + ReLU.  VALIDATED R11 SHAPE:
// 64oc x 64px block (one row), BK=8, 128 thr, 8(oc) x 4(px) register tiles.
// ---------------------------------------------------------------------------
__global__ void __launch_bounds__(128) conv3x3_relu(
    const float* __restrict__ x,      // (512,64,64)
    const float* __restrict__ w,      // (512,512,3,3)
    const float* __restrict__ bias)   // (512)
{
    __shared__ float Xs[8 * 3 * 66];                 // [icl][row][col -1..64]
    __shared__ __align__(16) float Ws[72 * 68];      // [icl*9+tap][oc]

    const int yrow = blockIdx.x;           // 0..63
    const int oc0  = blockIdx.y * 64;      // 8 tiles
    const int tid  = threadIdx.x;          // 0..127
    const int tx   = tid & 15;             // pixel group
    const int ty   = tid >> 4;             // oc group 0..7
    const int px0  = tx * 4;
    const int oc_t = ty * 8;

    float acc[8][4];
#pragma unroll
    for (int i = 0; i < 8; ++i)
#pragma unroll
        for (int j = 0; j < 4; ++j) acc[i][j] = 0.f;

    for (int ic0 = 0; ic0 < 512; ic0 += 8) {
        for (int idx = tid; idx < 8 * 3 * 66; idx += 128) {
            int icl = idx / 198;
            int rem = idx - icl * 198;
            int r   = rem / 66;
            int c   = rem - r * 66 - 1;        // -1..64
            int gy  = yrow - 1 + r;
            float v = 0.f;
            if ((unsigned)gy < 64u && (unsigned)c < 64u)
                v = x[(ic0 + icl) * 4096 + gy * 64 + c];
            Xs[idx] = v;
        }
        for (int idx = tid; idx < 64 * 72; idx += 128) {
            int oc = idx / 72;
            int r  = idx - oc * 72;            // icl*9 + tap
            Ws[r * 68 + oc] = w[(oc0 + oc) * 4608 + ic0 * 9 + r];
        }
        __syncthreads();

#pragma unroll 4
        for (int icl = 0; icl < 8; ++icl) {
#pragma unroll
            for (int kh = 0; kh < 3; ++kh) {
                float xv[6];
                const int xb = icl * 198 + kh * 66 + px0;
#pragma unroll
                for (int t = 0; t < 6; ++t) xv[t] = Xs[xb + t];
#pragma unroll
                for (int kw = 0; kw < 3; ++kw) {
                    const int wb = (icl * 9 + kh * 3 + kw) * 68 + oc_t;
                    const float4 wva = *reinterpret_cast<const float4*>(&Ws[wb]);
                    const float4 wvb = *reinterpret_cast<const float4*>(&Ws[wb + 4]);
                    const float w0 = wva.x, w1 = wva.y, w2 = wva.z, w3 = wva.w;
                    const float w4 = wvb.x, w5 = wvb.y, w6 = wvb.z, w7 = wvb.w;
#pragma unroll
                    for (int jx = 0; jx < 4; ++jx) {
                        float xvv = xv[kw + jx];
                        acc[0][jx] += w0 * xvv;
                        acc[1][jx] += w1 * xvv;
                        acc[2][jx] += w2 * xvv;
                        acc[3][jx] += w3 * xvv;
                        acc[4][jx] += w4 * xvv;
                        acc[5][jx] += w5 * xvv;
                        acc[6][jx] += w6 * xvv;
                        acc[7][jx] += w7 * xvv;
                    }
                }
            }
        }
        __syncthreads();
    }

#pragma unroll
    for (int i = 0; i < 8; ++i) {
        float b = bias[oc0 + oc_t + i];
#pragma unroll
        for (int jx = 0; jx < 4; ++jx) {
            float v = acc[i][jx] + b;
            g_y[(oc0 + oc_t + i) * 4096 + yrow * 64 + px0 + jx] = fmaxf(v, 0.f);
        }
    }
}

// ---------------------------------------------------------------------------
// 1x1 heads: cls (9) + box (36). VALIDATED R11 SHAPE: 32 blocks x 128 thr.
// ---------------------------------------------------------------------------
__global__ void __launch_bounds__(128) heads_kernel(
    const float* __restrict__ cw, const float* __restrict__ cb,
    const float* __restrict__ bw, const float* __restrict__ bb)
{
    __shared__ float ws[45 * 32];
    const int p = blockIdx.x * 128 + threadIdx.x;
    float acc[45];
#pragma unroll
    for (int c = 0; c < 45; ++c) acc[c] = 0.f;

    for (int ic0 = 0; ic0 < 512; ic0 += 32) {
        for (int idx = threadIdx.x; idx < 45 * 32; idx += 128) {
            int c = idx >> 5, icl = idx & 31;
            ws[idx] = (c < 9) ? cw[c * 512 + ic0 + icl]
                              : bw[(c - 9) * 512 + ic0 + icl];
        }
        __syncthreads();
        for (int icl = 0; icl < 32; ++icl) {
            float v = g_y[(ic0 + icl) * 4096 + p];
#pragma unroll
            for (int c = 0; c < 45; ++c) acc[c] += ws[c * 32 + icl] * v;
        }
        __syncthreads();
    }
#pragma unroll
    for (int a = 0; a < 9; ++a)  g_cls[a * 4096 + p] = acc[a] + cb[a];
#pragma unroll
    for (int c = 0; c < 36; ++c) g_box[c * 4096 + p] = acc[9 + c] + bb[c];
}

// ---------------------------------------------------------------------------
// Decode boxes (exact reshape(-1,4) aliasing), sigmoid, key + histogram.
// ---------------------------------------------------------------------------
__global__ void decode_kernel(const float* __restrict__ anchors)
{
    const int g = blockIdx.x * 256 + threadIdx.x;      // 144*256 == NPROP
    const int c  = g >> 10;
    const int p0 = (g & 1023) << 2;
    float dx = g_box[c * 4096 + p0 + 0];
    float dy = g_box[c * 4096 + p0 + 1];
    float dw = g_box[c * 4096 + p0 + 2];
    float dh = g_box[c * 4096 + p0 + 3];
    float ax1 = anchors[g * 4 + 0], ay1 = anchors[g * 4 + 1];
    float ax2 = anchors[g * 4 + 2], ay2 = anchors[g * 4 + 3];
    float aw = ax2 - ax1, ah = ay2 - ay1;
    float ax = ax1 + 0.5f * aw, ay = ay1 + 0.5f * ah;
    const float BBOX_CLIP = 4.135166556742356f;   // log(1000/16)
    dw = fminf(dw, BBOX_CLIP);
    dh = fminf(dh, BBOX_CLIP);
    float px = dx * aw + ax, py = dy * ah + ay;
    float pw = expf(dw) * aw, ph = expf(dh) * ah;
    g_preds[g * 4 + 0] = px - 0.5f * pw;
    g_preds[g * 4 + 1] = py - 0.5f * ph;
    g_preds[g * 4 + 2] = px + 0.5f * pw;
    g_preds[g * 4 + 3] = py + 0.5f * ph;

    float s = 1.f / (1.f + expf(-g_cls[g]));
    g_sig[g] = s;
    unsigned int u = __float_as_uint(s);
    u ^= (u & 0x80000000u) ? 0xFFFFFFFFu : 0x80000000u;   // ascending-monotone
    unsigned int kd = ~u;                                  // descending
    g_kd[g] = kd;
    atomicAdd(&g_hist[kd >> 12], 1);
}

// ---------------------------------------------------------------------------
// Coarse histogram sums: 1024 chunks of 512 bins.
// ---------------------------------------------------------------------------
__global__ void __launch_bounds__(256) hist_coarse()
{
    __shared__ int sred[256];
    const int b = blockIdx.x, t = threadIdx.x;
    int v = g_hist[b * 512 + t] + g_hist[b * 512 + 256 + t];
    sred[t] = v;
    __syncthreads();
    for (int d = 128; d > 0; d >>= 1) {
        if (t < d) sred[t] += sred[t + d];
        __syncthreads();
    }
    if (t == 0) g_coarse[b] = sred[0];
}

// ---------------------------------------------------------------------------
// Find cutoff bin: first bin B with cumulative(kd ascending) >= NPRE.
// ---------------------------------------------------------------------------
__global__ void __launch_bounds__(1024) findbin_kernel()
{
    __shared__ int s[1024];
    __shared__ int selblk, selbase;
    const int t = threadIdx.x;

    s[t] = g_coarse[t];
    __syncthreads();
    for (int d = 1; d < 1024; d <<= 1) {
        int v = s[t];
        int add = (t >= d) ? s[t - d] : 0;
        __syncthreads();
        s[t] = v + add;
        __syncthreads();
    }
    {
        int cum = s[t];
        int prev = (t == 0) ? 0 : s[t - 1];
        if (cum >= NPRE && prev < NPRE) { selblk = t; selbase = prev; }
    }
    __syncthreads();
    const int bb = selblk, base = selbase;

    __syncthreads();
    s[t] = (t < 512) ? g_hist[bb * 512 + t] : 0;
    __syncthreads();
    for (int d = 1; d < 1024; d <<= 1) {
        int v = s[t];
        int add = (t >= d) ? s[t - d] : 0;
        __syncthreads();
        s[t] = v + add;
        __syncthreads();
    }
    if (t < 512) {
        int cum = base + s[t];
        int prev = base + ((t == 0) ? 0 : s[t - 1]);
        if (cum >= NPRE && prev < NPRE) g_cut = bb * 512 + t;
    }
}

// ---------------------------------------------------------------------------
// Gather all items in bins <= cut (superset of exact top-6000).
// ---------------------------------------------------------------------------
__global__ void gather_kernel()
{
    const int g = blockIdx.x * 256 + threadIdx.x;      // == NPROP threads
    const unsigned int kd = g_kd[g];
    if ((int)(kd >> 12) <= g_cut) {
        int pos = atomicAdd(&g_cnt, 1);
        if (pos < NSEL)
            g_sel[pos] = ((unsigned long long)kd << 32) | (unsigned int)g;
    }
}

// ---------------------------------------------------------------------------
// Rank-by-counting over the <=8192 candidates; scatter ranks < 6000.
// ---------------------------------------------------------------------------
__global__ void __launch_bounds__(256) rank_scatter()
{
    __shared__ unsigned long long sk[2048];
    const int t = blockIdx.x * 256 + threadIdx.x;      // 32 blocks -> 8192
    const unsigned long long my = g_sel[t];
    int r = 0;
    for (int c0 = 0; c0 < NSEL; c0 += 2048) {
        for (int j = threadIdx.x; j < 2048; j += 256) sk[j] = g_sel[c0 + j];
        __syncthreads();
#pragma unroll 8
        for (int j = 0; j < 2048; ++j) r += (sk[j] < my) ? 1 : 0;
        __syncthreads();
    }
    if (r < NPRE) g_top[r] = my;
}

// ---------------------------------------------------------------------------
// Gather top-6000: clip to image, validity bits (ballot), score.
// ---------------------------------------------------------------------------
__global__ void __launch_bounds__(256) post_topk(const int* __restrict__ img)
{
    const int t = blockIdx.x * 256 + threadIdx.x;      // 24 blocks -> 6144
    bool valid = false;
    if (t < NPRE) {
        const unsigned long long key = g_top[t];
        const int g = (int)(key & 0xFFFFFFFFull);
        const float himg = (float)img[0], wimg = (float)img[1];
        float x1 = fminf(fmaxf(g_preds[g * 4 + 0], 0.f), wimg);
        float y1 = fminf(fmaxf(g_preds[g * 4 + 1], 0.f), himg);
        float x2 = fminf(fmaxf(g_preds[g * 4 + 2], 0.f), wimg);
        float y2 = fminf(fmaxf(g_preds[g * 4 + 3], 0.f), himg);
        g_b6k[t * 4 + 0] = x1;
        g_b6k[t * 4 + 1] = y1;
        g_b6k[t * 4 + 2] = x2;
        g_b6k[t * 4 + 3] = y2;
        g_v6k[t] = g_sig[g];
        valid = ((x2 - x1) >= 16.f) && ((y2 - y1) >= 16.f);
    }
    unsigned int bal = __ballot_sync(0xFFFFFFFFu, valid);
    if ((threadIdx.x & 31) == 0) g_valid32[t >> 5] = bal;
}

// ---------------------------------------------------------------------------
// NMS suppression bitmask, TRIANGULAR (g_mask pre-zeroed).
// mask[i][cb] bit jj set iff j>i and IoU(i,j)>0.7.
// ---------------------------------------------------------------------------
__global__ void __launch_bounds__(64) nms_mask()
{
    __shared__ float cbox[64 * 4];
    const int cb = blockIdx.x, rb = blockIdx.y;
    if (cb < rb) return;                   // lower triangle: all-zero words
    const int cbase = cb * 64;
    const int ccount = min(64, NPRE - cbase);
    if ((int)threadIdx.x < ccount) {
#pragma unroll
        for (int q = 0; q < 4; ++q)
            cbox[threadIdx.x * 4 + q] = g_b6k[(cbase + threadIdx.x) * 4 + q];
    }
    __syncthreads();
    const int i = rb * 64 + threadIdx.x;
    if (i >= NPRE) return;
    const float x1 = g_b6k[i * 4 + 0], y1 = g_b6k[i * 4 + 1];
    const float x2 = g_b6k[i * 4 + 2], y2 = g_b6k[i * 4 + 3];
    const float area_i = (x2 - x1) * (y2 - y1);
    unsigned long long bits = 0ull;
    for (int jj = 0; jj < ccount; ++jj) {
        int j = cbase + jj;
        if (j <= i) continue;
        float bx1 = cbox[jj * 4 + 0], by1 = cbox[jj * 4 + 1];
        float bx2 = cbox[jj * 4 + 2], by2 = cbox[jj * 4 + 3];
        float ix1 = fmaxf(x1, bx1), iy1 = fmaxf(y1, by1);
        float ix2 = fminf(x2, bx2), iy2 = fminf(y2, by2);
        float iw = fmaxf(ix2 - ix1, 0.f), ih = fmaxf(iy2 - iy1, 0.f);
        float inter = iw * ih;
        float uni = area_i + (bx2 - bx1) * (by2 - by1) - inter;
        float iou = (uni > 0.f) ? (inter / uni) : 0.f;
        if (iou > 0.7f) bits |= (1ull << jj);
    }
    g_mask[i * NW + cb] = bits;
}

// ---------------------------------------------------------------------------
// Greedy scan: single warp, removed-bits in registers, 8-deep prefetch,
// BATCHED aliveness: all 8 rows of a batch live in one rem word (8|64), so
// the intra-batch greedy chain is resolved locally on every lane
// speculatively; one shfl broadcasts the owner lane's 8-bit alive mask.
// Equivalent to row-serial greedy because masks only contain j>i bits.
// ---------------------------------------------------------------------------
__device__ __forceinline__ void scan_load8(
    unsigned long long (&buf)[8][3], int rowbase, int lane)
{
#pragma unroll
    for (int r = 0; r < 8; ++r) {
        const int i = rowbase + r;
        const bool ok = (i < NPRE);
        const unsigned long long* p = g_mask + (size_t)i * NW;
        buf[r][0] = ok ? p[lane] : 0ull;
        buf[r][1] = ok ? p[lane + 32] : 0ull;
        buf[r][2] = (ok && lane < 30) ? p[lane + 64] : 0ull;
    }
}

__device__ __forceinline__ void scan_proc8(
    const unsigned long long (&buf)[8][3], int base, int lane,
    unsigned long long (&rem)[3], unsigned long long (&keepw)[3])
{
    const int w    = base >> 6;            // same word for all 8 rows (8|64)
    const int src  = w & 31;
    const int slot = w >> 5;
    const int b0   = base & 63;

    // Speculative local greedy on every lane (only lane src's result used).
    unsigned long long localw = (slot == 0) ? rem[0]
                              : (slot == 1) ? rem[1] : rem[2];
    unsigned int am = 0;
#pragma unroll
    for (int r = 0; r < 8; ++r) {
        if (((localw >> (b0 + r)) & 1ull) == 0ull) {
            am |= (1u << r);
            localw |= (slot == 0) ? buf[r][0]
                    : (slot == 1) ? buf[r][1] : buf[r][2];
        }
    }
    am = __shfl_sync(0xFFFFFFFFu, am, src);

#pragma unroll
    for (int r = 0; r < 8; ++r) {
        if ((am >> r) & 1u) {
            rem[0] |= buf[r][0];
            rem[1] |= buf[r][1];
            rem[2] |= buf[r][2];
        }
    }
    if (lane == src) {
        if (slot == 0)      keepw[0] |= (unsigned long long)am << b0;
        else if (slot == 1) keepw[1] |= (unsigned long long)am << b0;
        else                keepw[2] |= (unsigned long long)am << b0;
    }
}

__global__ void __launch_bounds__(32) nms_scan_warp()
{
    const int lane = threadIdx.x;
    unsigned long long rem[3], keepw[3] = {0ull, 0ull, 0ull};
#pragma unroll
    for (int s = 0; s < 3; ++s) {
        const int w = lane + 32 * s;
        if (w < NW) {
            unsigned long long lo = g_valid32[2 * w];
            unsigned long long hi = g_valid32[2 * w + 1];
            rem[s] = ~((hi << 32) | lo);
        } else {
            rem[s] = ~0ull;
        }
    }
    unsigned long long A[8][3], B[8][3];
    scan_load8(A, 0, lane);
    for (int base = 0; base < NPRE; base += 16) {
        scan_load8(B, base + 8, lane);
        scan_proc8(A, base, lane, rem, keepw);
        scan_load8(A, base + 16, lane);
        scan_proc8(B, base + 8, lane, rem, keepw);
    }
#pragma unroll
    for (int s = 0; s < 3; ++s) {
        const int w = lane + 32 * s;
        if (w < NW) g_keepbits[w] = keepw[s];
    }
}

// ---------------------------------------------------------------------------
// Finalize: kept entries in order, then suppressed by ascending index with
// score -1; first 300 -> out (boxes [300,4] then scores [300]).
// ---------------------------------------------------------------------------
__global__ void __launch_bounds__(256) finalize(float* __restrict__ out)
{
    __shared__ int ckeep[256], csupp[256];
    __shared__ int okeep[256], osupp[256];
    __shared__ int totk;
    const int t = threadIdx.x;
    const int beg = t * 24;
    const int end = min(beg + 24, NPRE);
    int ck = 0;
    for (int i = beg; i < end; ++i)
        ck += (int)((g_keepbits[i >> 6] >> (i & 63)) & 1ull);
    ckeep[t] = ck;
    csupp[t] = (end > beg ? (end - beg) : 0) - ck;
    __syncthreads();
    if (t == 0) {
        int a = 0, b = 0;
        for (int q = 0; q < 256; ++q) {
            okeep[q] = a; osupp[q] = b;
            a += ckeep[q]; b += csupp[q];
        }
        totk = a;
    }
    __syncthreads();
    int rk = okeep[t];
    int rs = totk + osupp[t];
    for (int i = beg; i < end; ++i) {
        bool kp = ((g_keepbits[i >> 6] >> (i & 63)) & 1ull) != 0ull;
        int rank = kp ? (rk++) : (rs++);
        if (rank < NPOST) {
            out[rank * 4 + 0] = g_b6k[i * 4 + 0];
            out[rank * 4 + 1] = g_b6k[i * 4 + 1];
            out[rank * 4 + 2] = g_b6k[i * 4 + 2];
            out[rank * 4 + 3] = g_b6k[i * 4 + 3];
            out[NPOST * 4 + rank] = kp ? g_v6k[i] : -1.0f;
        }
    }
}

// ---------------------------------------------------------------------------
extern "C" void kernel_launch(void* const* d_in, const int* in_sizes, int n_in,
                              void* d_out, int out_size)
{
    const float* feature = (const float*)d_in[0];   // (1,512,64,64)
    const float* anchors = (const float*)d_in[1];   // (36864,4)
    const int*   imgsh   = (const int*)d_in[2];     // (2,)
    const float* c1w     = (const float*)d_in[3];   // (512,512,3,3)
    const float* c1b     = (const float*)d_in[4];   // (512,)
    const float* clsw    = (const float*)d_in[5];   // (9,512,1,1)
    const float* clsb    = (const float*)d_in[6];   // (9,)
    const float* boxw    = (const float*)d_in[7];   // (36,512,1,1)
    const float* boxb    = (const float*)d_in[8];   // (36,)
    float* out = (float*)d_out;                     // 1500 floats

    memset_a<<<256, 256>>>();                       // launch 1
    memset_b<<<256, 256>>>();                       // launch 2
    memset_c<<<1, 256>>>();                         // launch 3
    conv3x3_relu<<<dim3(64, 8), 128>>>(feature, c1w, c1b);   // launch 4 (profiled)
    heads_kernel<<<32, 128>>>(clsw, clsb, boxw, boxb);
    decode_kernel<<<NPROP / 256, 256>>>(anchors);
    hist_coarse<<<1024, 256>>>();
    findbin_kernel<<<1, 1024>>>();
    gather_kernel<<<NPROP / 256, 256>>>();
    rank_scatter<<<NSEL / 256, 256>>>();
    post_topk<<<24, 256>>>(imgsh);
    nms_mask<<<dim3(NW, NW), 64>>>();
    nms_scan_warp<<<1, 32>>>();
    finalize<<<1, 256>>>(out);
}